// round 1
// baseline (speedup 1.0000x reference)
#include <cuda_runtime.h>
#include <stdint.h>

// |diag(W)| scratch (no cudaMalloc allowed)
__device__ float g_diag[1024];

__global__ void extract_diag_kernel(const float* __restrict__ W, int D) {
    int i = blockIdx.x * blockDim.x + threadIdx.x;
    if (i < D) {
        g_diag[i] = fabsf(W[(size_t)i * D + i]);
    }
}

// Streaming multiply: out[b,d] = x[b,d] * diag[d], vectorized float4.
// D = 1024 -> 256 float4 column groups; col group = idx & 255.
__global__ void diag_mul_kernel(const float4* __restrict__ x4,
                                float4* __restrict__ out4,
                                long n4) {
    __shared__ float4 s_d[256];
    // load diag into shared once per block (blockDim.x == 256)
    s_d[threadIdx.x] = reinterpret_cast<const float4*>(g_diag)[threadIdx.x];
    __syncthreads();

    long stride = (long)gridDim.x * blockDim.x;
    for (long i = (long)blockIdx.x * blockDim.x + threadIdx.x; i < n4; i += stride) {
        float4 v = x4[i];
        float4 d = s_d[(int)(i & 255)];
        v.x *= d.x;
        v.y *= d.y;
        v.z *= d.z;
        v.w *= d.w;
        out4[i] = v;
    }
}

extern "C" void kernel_launch(void* const* d_in, const int* in_sizes, int n_in,
                              void* d_out, int out_size) {
    const float* x = (const float*)d_in[0];
    const float* W = (const float*)d_in[1];
    float* out = (float*)d_out;

    const int D = 1024;
    const long total = (long)out_size;       // 65536 * 1024
    const long n4 = total / 4;               // 16,777,216 float4s

    extract_diag_kernel<<<4, 256>>>(W, D);

    // 148 SMs; give each SM several blocks for latency hiding, grid-stride covers the rest.
    int blocks = 148 * 16;  // 2368 blocks x 256 threads -> ~27 float4 per thread
    diag_mul_kernel<<<blocks, 256>>>(
        reinterpret_cast<const float4*>(x),
        reinterpret_cast<float4*>(out),
        n4);
}